// round 2
// baseline (speedup 1.0000x reference)
#include <cuda_runtime.h>
#include <cuda_bf16.h>
#include <math.h>

// Problem constants
#define Bsz 2
#define Tq  2048
#define Dm  1024
#define Hh  16
#define DH  64   // Dm / Hh

// ---------------------------------------------------------------------------
// Scratch (allocation-free rule: __device__ globals)
// ---------------------------------------------------------------------------
__device__ float g_q [Bsz * Tq * Dm];
__device__ float g_k [Bsz * Tq * Dm];
__device__ float g_v [Bsz * Tq * Dm];
__device__ float g_ao[Bsz * Tq * Dm];

// ---------------------------------------------------------------------------
// SGEMM: C[M,N] = A[M,K] @ B[K,N], fp32, row-major.
// BM=BN=64, BK=16, 256 threads, 4x4 register tile per thread.
// M=4096, N=K=1024 for all four projection GEMMs.
// ---------------------------------------------------------------------------
__global__ __launch_bounds__(256)
void sgemm64(const float* __restrict__ A, const float* __restrict__ B,
             float* __restrict__ C, int M, int N, int K)
{
    __shared__ float As[64][20];  // [m][k], pad 20 -> conflict-free f4 stores
    __shared__ float Bs[16][68];  // [k][n], pad 68 -> stride%32==4 (2-way max)

    const int tx = threadIdx.x & 15;   // n-dim
    const int ty = threadIdx.x >> 4;   // m-dim
    const int bm = blockIdx.y * 64;
    const int bn = blockIdx.x * 64;

    float acc[4][4] = {};

    for (int k0 = 0; k0 < K; k0 += 16) {
        // Load A tile 64x16 (256 float4, one per thread)
        {
            int r  = threadIdx.x >> 2;
            int c4 = threadIdx.x & 3;
            float4 v = *(const float4*)(A + (size_t)(bm + r) * K + k0 + c4 * 4);
            *(float4*)&As[r][c4 * 4] = v;
        }
        // Load B tile 16x64 (256 float4, one per thread)
        {
            int r  = threadIdx.x >> 4;
            int c4 = threadIdx.x & 15;
            float4 v = *(const float4*)(B + (size_t)(k0 + r) * N + bn + c4 * 4);
            *(float4*)&Bs[r][c4 * 4] = v;
        }
        __syncthreads();

#pragma unroll
        for (int k = 0; k < 16; k++) {
            float a[4];
#pragma unroll
            for (int i = 0; i < 4; i++) a[i] = As[ty * 4 + i][k];
            float4 b4 = *(const float4*)&Bs[k][tx * 4];
            float b[4] = {b4.x, b4.y, b4.z, b4.w};
#pragma unroll
            for (int i = 0; i < 4; i++)
#pragma unroll
                for (int j = 0; j < 4; j++)
                    acc[i][j] = fmaf(a[i], b[j], acc[i][j]);
        }
        __syncthreads();
    }

#pragma unroll
    for (int i = 0; i < 4; i++) {
        float4 v = make_float4(acc[i][0], acc[i][1], acc[i][2], acc[i][3]);
        *(float4*)(C + (size_t)(bm + ty * 4 + i) * N + bn + tx * 4) = v;
    }
}

// ---------------------------------------------------------------------------
// Causal flash attention, fp32.
// Grid: (T/64, B*H). Block: 256 threads (16x16 logical), 4x4 reg tiles.
// Q/K/V layout: [B, T, D] with head h occupying cols [h*64, h*64+64).
// Online softmax; only kt <= qt tiles processed (causal skip).
// Dynamic smem: Qs + Ks + Vs + Ps, each 64 x 68 floats = 69632 B total.
// ---------------------------------------------------------------------------
__global__ __launch_bounds__(256)
void attn_causal(const float* __restrict__ Q, const float* __restrict__ K,
                 const float* __restrict__ V, float* __restrict__ O)
{
    extern __shared__ float sm[];
    float (*Qs)[68] = (float(*)[68])(sm);
    float (*Ks)[68] = (float(*)[68])(sm + 64 * 68);
    float (*Vs)[68] = (float(*)[68])(sm + 2 * 64 * 68);
    float (*Ps)[68] = (float(*)[68])(sm + 3 * 64 * 68);

    const int tx = threadIdx.x & 15;   // key/dh dim
    const int ty = threadIdx.x >> 4;   // query dim
    const int qt = blockIdx.x;         // query tile
    const int bh = blockIdx.y;
    const int b  = bh >> 4;
    const int h  = bh & 15;
    const int q0 = qt * 64;

    const float scale = 0.125f;        // 1/sqrt(64)
    const size_t headoff = (size_t)b * Tq * Dm + (size_t)h * DH;

    // Load Q tile (scaled). 1024 float4s over 256 threads.
    {
        const float* Qbase = Q + headoff + (size_t)q0 * Dm;
        for (int i = threadIdx.x; i < 64 * 16; i += 256) {
            int r = i >> 4, c4 = i & 15;
            float4 v = *(const float4*)(Qbase + (size_t)r * Dm + c4 * 4);
            v.x *= scale; v.y *= scale; v.z *= scale; v.w *= scale;
            *(float4*)&Qs[r][c4 * 4] = v;
        }
    }
    __syncthreads();

    float m_i[4], l_i[4], oacc[4][4];
#pragma unroll
    for (int i = 0; i < 4; i++) {
        m_i[i] = -INFINITY; l_i[i] = 0.f;
#pragma unroll
        for (int j = 0; j < 4; j++) oacc[i][j] = 0.f;
    }

    for (int kt = 0; kt <= qt; kt++) {
        // Load K and V tiles
        {
            const float* Kbase = K + headoff + (size_t)(kt * 64) * Dm;
            const float* Vbase = V + headoff + (size_t)(kt * 64) * Dm;
            for (int i = threadIdx.x; i < 64 * 16; i += 256) {
                int r = i >> 4, c4 = i & 15;
                *(float4*)&Ks[r][c4 * 4] = *(const float4*)(Kbase + (size_t)r * Dm + c4 * 4);
                *(float4*)&Vs[r][c4 * 4] = *(const float4*)(Vbase + (size_t)r * Dm + c4 * 4);
            }
        }
        __syncthreads();

        // S = Q K^T : 4x4 per thread over d=64
        float s[4][4] = {};
#pragma unroll
        for (int d4 = 0; d4 < 16; d4++) {
            float4 q4[4], k4[4];
#pragma unroll
            for (int i = 0; i < 4; i++) q4[i] = *(const float4*)&Qs[ty * 4 + i][d4 * 4];
#pragma unroll
            for (int j = 0; j < 4; j++) k4[j] = *(const float4*)&Ks[tx * 4 + j][d4 * 4];
#pragma unroll
            for (int i = 0; i < 4; i++)
#pragma unroll
                for (int j = 0; j < 4; j++) {
                    s[i][j] = fmaf(q4[i].x, k4[j].x, s[i][j]);
                    s[i][j] = fmaf(q4[i].y, k4[j].y, s[i][j]);
                    s[i][j] = fmaf(q4[i].z, k4[j].z, s[i][j]);
                    s[i][j] = fmaf(q4[i].w, k4[j].w, s[i][j]);
                }
        }

        // Causal mask on the diagonal tile (local row m vs local col n)
        if (kt == qt) {
#pragma unroll
            for (int i = 0; i < 4; i++)
#pragma unroll
                for (int j = 0; j < 4; j++)
                    if (tx * 4 + j > ty * 4 + i) s[i][j] = -INFINITY;
        }

        // Online softmax (row reductions across the 16 tx-lanes of each half-warp)
#pragma unroll
        for (int i = 0; i < 4; i++) {
            float rmax = fmaxf(fmaxf(s[i][0], s[i][1]), fmaxf(s[i][2], s[i][3]));
#pragma unroll
            for (int w = 1; w <= 8; w <<= 1)
                rmax = fmaxf(rmax, __shfl_xor_sync(0xffffffffu, rmax, w));

            float mn = fmaxf(m_i[i], rmax);
            float sc = __expf(m_i[i] - mn);   // 0 when m_i == -inf
            m_i[i] = mn;

            float p0 = __expf(s[i][0] - mn);
            float p1 = __expf(s[i][1] - mn);
            float p2 = __expf(s[i][2] - mn);
            float p3 = __expf(s[i][3] - mn);
            float rsum = p0 + p1 + p2 + p3;
#pragma unroll
            for (int w = 1; w <= 8; w <<= 1)
                rsum += __shfl_xor_sync(0xffffffffu, rsum, w);
            l_i[i] = l_i[i] * sc + rsum;

#pragma unroll
            for (int j = 0; j < 4; j++) oacc[i][j] *= sc;

            *(float4*)&Ps[ty * 4 + i][tx * 4] = make_float4(p0, p1, p2, p3);
        }
        __syncthreads();

        // O += P @ V  (inner dim n=64)
#pragma unroll 8
        for (int n = 0; n < 64; n++) {
            float4 v4 = *(const float4*)&Vs[n][tx * 4];
            float pr[4];
#pragma unroll
            for (int i = 0; i < 4; i++) pr[i] = Ps[ty * 4 + i][n];
#pragma unroll
            for (int i = 0; i < 4; i++) {
                oacc[i][0] = fmaf(pr[i], v4.x, oacc[i][0]);
                oacc[i][1] = fmaf(pr[i], v4.y, oacc[i][1]);
                oacc[i][2] = fmaf(pr[i], v4.z, oacc[i][2]);
                oacc[i][3] = fmaf(pr[i], v4.w, oacc[i][3]);
            }
        }
        __syncthreads();
    }

    // Normalize and write out [B, T, D] (heads re-merged in place)
#pragma unroll
    for (int i = 0; i < 4; i++) {
        float inv = 1.0f / l_i[i];
        float4 v = make_float4(oacc[i][0] * inv, oacc[i][1] * inv,
                               oacc[i][2] * inv, oacc[i][3] * inv);
        *(float4*)(O + headoff + (size_t)(q0 + ty * 4 + i) * Dm + tx * 4) = v;
    }
}

// ---------------------------------------------------------------------------
// Launch: x@Wq, x@Wk, x@Wv -> attention -> @Wo
// Inputs (metadata order): 0=x, 1=mask(unused, causal is hardcoded),
//                          2=Wq, 3=Wk, 4=Wv, 5=Wo
// ---------------------------------------------------------------------------
extern "C" void kernel_launch(void* const* d_in, const int* in_sizes, int n_in,
                              void* d_out, int out_size)
{
    const float* x  = (const float*)d_in[0];
    const float* Wq = (const float*)d_in[2];
    const float* Wk = (const float*)d_in[3];
    const float* Wv = (const float*)d_in[4];
    const float* Wo = (const float*)d_in[5];
    float* out = (float*)d_out;

    void *pq, *pk, *pv, *pao;
    cudaGetSymbolAddress(&pq,  g_q);
    cudaGetSymbolAddress(&pk,  g_k);
    cudaGetSymbolAddress(&pv,  g_v);
    cudaGetSymbolAddress(&pao, g_ao);

    static_assert(4 * 64 * 68 * sizeof(float) == 69632, "smem size");
    cudaFuncSetAttribute(attn_causal, cudaFuncAttributeMaxDynamicSharedMemorySize, 69632);

    const int M = Bsz * Tq;   // 4096
    dim3 gGemm(Dm / 64, M / 64);   // (16, 64)
    dim3 gAttn(Tq / 64, Bsz * Hh); // (32, 32)

    sgemm64<<<gGemm, 256>>>(x, Wq, (float*)pq, M, Dm, Dm);
    sgemm64<<<gGemm, 256>>>(x, Wk, (float*)pk, M, Dm, Dm);
    sgemm64<<<gGemm, 256>>>(x, Wv, (float*)pv, M, Dm, Dm);
    attn_causal<<<gAttn, 256, 69632>>>((const float*)pq, (const float*)pk,
                                       (const float*)pv, (float*)pao);
    sgemm64<<<gGemm, 256>>>((const float*)pao, Wo, out, M, Dm, Dm);
}

// round 4
// speedup vs baseline: 1.5224x; 1.5224x over previous
#include <cuda_runtime.h>
#include <cuda_bf16.h>
#include <math.h>
#include <cstdint>

// Problem constants
#define Bsz 2
#define Tq  2048
#define Dm  1024
#define Hh  16
#define DH  64

// ---------------------------------------------------------------------------
// Scratch (allocation-free rule: __device__ globals)
// ---------------------------------------------------------------------------
__device__ float g_q [Bsz * Tq * Dm];
__device__ float g_k [Bsz * Tq * Dm];
__device__ float g_v [Bsz * Tq * Dm];
__device__ float g_ao[Bsz * Tq * Dm];

// ---------------------------------------------------------------------------
// Helpers
// ---------------------------------------------------------------------------
__device__ __forceinline__ uint32_t smem_to_u32(const void* p) {
    uint32_t a;
    asm("{ .reg .u64 t; cvta.to.shared.u64 t, %1; cvt.u32.u64 %0, t; }"
        : "=r"(a) : "l"(p));
    return a;
}
__device__ __forceinline__ uint32_t f2tf32(float f) {
    uint32_t r;
    asm("cvt.rna.tf32.f32 %0, %1;" : "=r"(r) : "f"(f));
    return r;
}
__device__ __forceinline__ void mma_tf32(float* c,
                                         uint32_t a0, uint32_t a1, uint32_t a2, uint32_t a3,
                                         uint32_t b0, uint32_t b1)
{
    asm volatile(
        "mma.sync.aligned.m16n8k8.row.col.f32.tf32.tf32.f32 "
        "{%0,%1,%2,%3}, {%4,%5,%6,%7}, {%8,%9}, {%0,%1,%2,%3};"
        : "+f"(c[0]), "+f"(c[1]), "+f"(c[2]), "+f"(c[3])
        : "r"(a0), "r"(a1), "r"(a2), "r"(a3), "r"(b0), "r"(b1));
}

// ---------------------------------------------------------------------------
// GEMM via mma.sync tf32: C[4096,1024] = A[4096,1024] @ W[1024,1024]
// CTA 128x128, BK=32, 256 threads (8 warps, warp tile 32x64), double-buffered.
// A smem: row-major [128][36] tf32-bits (pad 36 -> conflict-free frag LDS).
// B smem: fragment-order [ntile(16)][ktile(4)][lane(32)][slot(2)] u32 with
//         lane^ntile swizzle; built straight from W rows (B[k][n] = W[k][n]).
// ---------------------------------------------------------------------------
#define GM_BM 128
#define GM_BN 128
#define GM_BK 32

#define SA_BYTES (128 * 36 * 4)          // 18432
#define SB_BYTES (16 * 4 * 32 * 8)       // 16384
#define SA0 0
#define SB0 SA_BYTES
#define SA1 (SB0 + SB_BYTES)
#define SB1 (SA1 + SA_BYTES)
#define SMEM_GEMM (SB1 + SB_BYTES)       // 69632

__global__ __launch_bounds__(256)
void gemm_mma(const float* __restrict__ A, const float* __restrict__ W,
              float* __restrict__ C)
{
    extern __shared__ char smem[];
    const uint32_t sb  = smem_to_u32(smem);
    const int tid  = threadIdx.x;
    const int lane = tid & 31;
    const int wid  = tid >> 5;
    const int wm   = wid & 3;
    const int wn   = wid >> 2;
    const int bm   = blockIdx.y * GM_BM;
    const int bn   = blockIdx.x * GM_BN;

    float acc[2][8][4];
#pragma unroll
    for (int i = 0; i < 2; i++)
#pragma unroll
        for (int j = 0; j < 8; j++)
#pragma unroll
            for (int q = 0; q < 4; q++) acc[i][j][q] = 0.f;

    float4 stA[4], stB[4];

    auto LDG = [&](int k0) {
#pragma unroll
        for (int it = 0; it < 4; it++) {
            int i = tid + it * 256;
            stA[it] = *(const float4*)(A + (size_t)(bm + (i >> 3)) * Dm + k0 + (i & 7) * 4);
        }
#pragma unroll
        for (int it = 0; it < 4; it++) {
            int i = tid + it * 256;
            stB[it] = *(const float4*)(W + (size_t)(k0 + (i >> 5)) * Dm + bn + (i & 31) * 4);
        }
    };

    auto STS = [&](uint32_t sa, uint32_t sbb) {
#pragma unroll
        for (int it = 0; it < 4; it++) {
            int i = tid + it * 256;
            int r = i >> 3, c4 = i & 7;
            uint32_t ad = sa + (uint32_t)(r * 144 + c4 * 16);
            asm volatile("st.shared.v4.b32 [%0], {%1,%2,%3,%4};" :: "r"(ad),
                "r"(f2tf32(stA[it].x)), "r"(f2tf32(stA[it].y)),
                "r"(f2tf32(stA[it].z)), "r"(f2tf32(stA[it].w)) : "memory");
        }
#pragma unroll
        for (int it = 0; it < 4; it++) {
            int i = tid + it * 256;
            int k = i >> 5, n4 = i & 31;
            int ktile = k >> 3, kk = k & 7;
            int slot = kk >> 2, kb = kk & 3;
            int ntile = n4 >> 1, nnb = (n4 & 1) << 2;
            uint32_t tb = sbb + (uint32_t)((ntile * 4 + ktile) * 256 + slot * 4);
            uint32_t l0 = (uint32_t)((((nnb + 0) << 2) | kb) ^ ntile);
            uint32_t l1 = (uint32_t)((((nnb + 1) << 2) | kb) ^ ntile);
            uint32_t l2 = (uint32_t)((((nnb + 2) << 2) | kb) ^ ntile);
            uint32_t l3 = (uint32_t)((((nnb + 3) << 2) | kb) ^ ntile);
            asm volatile("st.shared.b32 [%0], %1;" :: "r"(tb + l0 * 8), "r"(f2tf32(stB[it].x)) : "memory");
            asm volatile("st.shared.b32 [%0], %1;" :: "r"(tb + l1 * 8), "r"(f2tf32(stB[it].y)) : "memory");
            asm volatile("st.shared.b32 [%0], %1;" :: "r"(tb + l2 * 8), "r"(f2tf32(stB[it].z)) : "memory");
            asm volatile("st.shared.b32 [%0], %1;" :: "r"(tb + l3 * 8), "r"(f2tf32(stB[it].w)) : "memory");
        }
    };

    auto COMPUTE = [&](uint32_t sa, uint32_t sbb) {
#pragma unroll
        for (int ks = 0; ks < 4; ks++) {
            uint32_t af[2][4];
#pragma unroll
            for (int i = 0; i < 2; i++) {
                int row = wm * 32 + i * 16 + (lane >> 2);
                int col = ks * 8 + (lane & 3);
                uint32_t base = sa + (uint32_t)(row * 144 + col * 4);
                asm volatile("ld.shared.b32 %0, [%1];" : "=r"(af[i][0]) : "r"(base));
                asm volatile("ld.shared.b32 %0, [%1];" : "=r"(af[i][1]) : "r"(base + 8 * 144));
                asm volatile("ld.shared.b32 %0, [%1];" : "=r"(af[i][2]) : "r"(base + 16));
                asm volatile("ld.shared.b32 %0, [%1];" : "=r"(af[i][3]) : "r"(base + 8 * 144 + 16));
            }
            uint32_t bf[8][2];
#pragma unroll
            for (int j = 0; j < 8; j++) {
                int nt = wn * 8 + j;
                uint32_t ad = sbb + (uint32_t)((nt * 4 + ks) * 256 + ((lane ^ nt) & 31) * 8);
                asm volatile("ld.shared.v2.b32 {%0,%1}, [%2];"
                             : "=r"(bf[j][0]), "=r"(bf[j][1]) : "r"(ad));
            }
#pragma unroll
            for (int i = 0; i < 2; i++)
#pragma unroll
                for (int j = 0; j < 8; j++)
                    mma_tf32(acc[i][j], af[i][0], af[i][1], af[i][2], af[i][3],
                             bf[j][0], bf[j][1]);
        }
    };

    LDG(0);
    STS(sb + SA0, sb + SB0);
    __syncthreads();

#pragma unroll 1
    for (int ch = 0; ch < Dm / GM_BK; ch++) {
        const int p = ch & 1;
        if (ch + 1 < Dm / GM_BK) LDG((ch + 1) * GM_BK);
        COMPUTE(sb + (p ? SA1 : SA0), sb + (p ? SB1 : SB0));
        if (ch + 1 < Dm / GM_BK) STS(sb + (p ? SA0 : SA1), sb + (p ? SB0 : SB1));
        __syncthreads();
    }

#pragma unroll
    for (int i = 0; i < 2; i++) {
        int r0 = bm + wm * 32 + i * 16 + (lane >> 2);
#pragma unroll
        for (int j = 0; j < 8; j++) {
            int c = bn + wn * 64 + j * 8 + (lane & 3) * 2;
            *(float2*)(C + (size_t)r0 * Dm + c)       = make_float2(acc[i][j][0], acc[i][j][1]);
            *(float2*)(C + (size_t)(r0 + 8) * Dm + c) = make_float2(acc[i][j][2], acc[i][j][3]);
        }
    }
}

// ---------------------------------------------------------------------------
// Causal flash attention, fp32 (unchanged from R2)
// ---------------------------------------------------------------------------
__global__ __launch_bounds__(256)
void attn_causal(const float* __restrict__ Q, const float* __restrict__ K,
                 const float* __restrict__ V, float* __restrict__ O)
{
    extern __shared__ float sm[];
    float (*Qs)[68] = (float(*)[68])(sm);
    float (*Ks)[68] = (float(*)[68])(sm + 64 * 68);
    float (*Vs)[68] = (float(*)[68])(sm + 2 * 64 * 68);
    float (*Ps)[68] = (float(*)[68])(sm + 3 * 64 * 68);

    const int tx = threadIdx.x & 15;
    const int ty = threadIdx.x >> 4;
    const int qt = blockIdx.x;
    const int bh = blockIdx.y;
    const int b  = bh >> 4;
    const int h  = bh & 15;
    const int q0 = qt * 64;

    const float scale = 0.125f;
    const size_t headoff = (size_t)b * Tq * Dm + (size_t)h * DH;

    {
        const float* Qbase = Q + headoff + (size_t)q0 * Dm;
        for (int i = threadIdx.x; i < 64 * 16; i += 256) {
            int r = i >> 4, c4 = i & 15;
            float4 v = *(const float4*)(Qbase + (size_t)r * Dm + c4 * 4);
            v.x *= scale; v.y *= scale; v.z *= scale; v.w *= scale;
            *(float4*)&Qs[r][c4 * 4] = v;
        }
    }
    __syncthreads();

    float m_i[4], l_i[4], oacc[4][4];
#pragma unroll
    for (int i = 0; i < 4; i++) {
        m_i[i] = -INFINITY; l_i[i] = 0.f;
#pragma unroll
        for (int j = 0; j < 4; j++) oacc[i][j] = 0.f;
    }

    for (int kt = 0; kt <= qt; kt++) {
        {
            const float* Kbase = K + headoff + (size_t)(kt * 64) * Dm;
            const float* Vbase = V + headoff + (size_t)(kt * 64) * Dm;
            for (int i = threadIdx.x; i < 64 * 16; i += 256) {
                int r = i >> 4, c4 = i & 15;
                *(float4*)&Ks[r][c4 * 4] = *(const float4*)(Kbase + (size_t)r * Dm + c4 * 4);
                *(float4*)&Vs[r][c4 * 4] = *(const float4*)(Vbase + (size_t)r * Dm + c4 * 4);
            }
        }
        __syncthreads();

        float s[4][4] = {};
#pragma unroll
        for (int d4 = 0; d4 < 16; d4++) {
            float4 q4[4], k4[4];
#pragma unroll
            for (int i = 0; i < 4; i++) q4[i] = *(const float4*)&Qs[ty * 4 + i][d4 * 4];
#pragma unroll
            for (int j = 0; j < 4; j++) k4[j] = *(const float4*)&Ks[tx * 4 + j][d4 * 4];
#pragma unroll
            for (int i = 0; i < 4; i++)
#pragma unroll
                for (int j = 0; j < 4; j++) {
                    s[i][j] = fmaf(q4[i].x, k4[j].x, s[i][j]);
                    s[i][j] = fmaf(q4[i].y, k4[j].y, s[i][j]);
                    s[i][j] = fmaf(q4[i].z, k4[j].z, s[i][j]);
                    s[i][j] = fmaf(q4[i].w, k4[j].w, s[i][j]);
                }
        }

        if (kt == qt) {
#pragma unroll
            for (int i = 0; i < 4; i++)
#pragma unroll
                for (int j = 0; j < 4; j++)
                    if (tx * 4 + j > ty * 4 + i) s[i][j] = -INFINITY;
        }

#pragma unroll
        for (int i = 0; i < 4; i++) {
            float rmax = fmaxf(fmaxf(s[i][0], s[i][1]), fmaxf(s[i][2], s[i][3]));
#pragma unroll
            for (int w = 1; w <= 8; w <<= 1)
                rmax = fmaxf(rmax, __shfl_xor_sync(0xffffffffu, rmax, w));

            float mn = fmaxf(m_i[i], rmax);
            float sc = __expf(m_i[i] - mn);
            m_i[i] = mn;

            float p0 = __expf(s[i][0] - mn);
            float p1 = __expf(s[i][1] - mn);
            float p2 = __expf(s[i][2] - mn);
            float p3 = __expf(s[i][3] - mn);
            float rsum = p0 + p1 + p2 + p3;
#pragma unroll
            for (int w = 1; w <= 8; w <<= 1)
                rsum += __shfl_xor_sync(0xffffffffu, rsum, w);
            l_i[i] = l_i[i] * sc + rsum;

#pragma unroll
            for (int j = 0; j < 4; j++) oacc[i][j] *= sc;

            *(float4*)&Ps[ty * 4 + i][tx * 4] = make_float4(p0, p1, p2, p3);
        }
        __syncthreads();

#pragma unroll 8
        for (int n = 0; n < 64; n++) {
            float4 v4 = *(const float4*)&Vs[n][tx * 4];
            float pr[4];
#pragma unroll
            for (int i = 0; i < 4; i++) pr[i] = Ps[ty * 4 + i][n];
#pragma unroll
            for (int i = 0; i < 4; i++) {
                oacc[i][0] = fmaf(pr[i], v4.x, oacc[i][0]);
                oacc[i][1] = fmaf(pr[i], v4.y, oacc[i][1]);
                oacc[i][2] = fmaf(pr[i], v4.z, oacc[i][2]);
                oacc[i][3] = fmaf(pr[i], v4.w, oacc[i][3]);
            }
        }
        __syncthreads();
    }

#pragma unroll
    for (int i = 0; i < 4; i++) {
        float inv = 1.0f / l_i[i];
        float4 v = make_float4(oacc[i][0] * inv, oacc[i][1] * inv,
                               oacc[i][2] * inv, oacc[i][3] * inv);
        *(float4*)(O + headoff + (size_t)(q0 + ty * 4 + i) * Dm + tx * 4) = v;
    }
}

// ---------------------------------------------------------------------------
// Launch.  Inputs: 0=x, 1=mask(unused), 2=Wq, 3=Wk, 4=Wv, 5=Wo
// ---------------------------------------------------------------------------
extern "C" void kernel_launch(void* const* d_in, const int* in_sizes, int n_in,
                              void* d_out, int out_size)
{
    const float* x  = (const float*)d_in[0];
    const float* Wq = (const float*)d_in[2];
    const float* Wk = (const float*)d_in[3];
    const float* Wv = (const float*)d_in[4];
    const float* Wo = (const float*)d_in[5];
    float* out = (float*)d_out;

    void *pq, *pk, *pv, *pao;
    cudaGetSymbolAddress(&pq,  g_q);
    cudaGetSymbolAddress(&pk,  g_k);
    cudaGetSymbolAddress(&pv,  g_v);
    cudaGetSymbolAddress(&pao, g_ao);

    cudaFuncSetAttribute(attn_causal, cudaFuncAttributeMaxDynamicSharedMemorySize, 69632);
    cudaFuncSetAttribute(gemm_mma,    cudaFuncAttributeMaxDynamicSharedMemorySize, SMEM_GEMM);

    const int M = Bsz * Tq;                 // 4096
    dim3 gG(Dm / GM_BN, M / GM_BM);         // (8, 32) = 256 CTAs
    dim3 gAttn(Tq / 64, Bsz * Hh);          // (32, 32)

    gemm_mma<<<gG, 256, SMEM_GEMM>>>(x, Wq, (float*)pq);
    gemm_mma<<<gG, 256, SMEM_GEMM>>>(x, Wk, (float*)pk);
    gemm_mma<<<gG, 256, SMEM_GEMM>>>(x, Wv, (float*)pv);

    attn_causal<<<gAttn, 256, 69632>>>((const float*)pq, (const float*)pk,
                                       (const float*)pv, (float*)pao);

    gemm_mma<<<gG, 256, SMEM_GEMM>>>((const float*)pao, Wo, out);
}

// round 5
// speedup vs baseline: 3.3889x; 2.2260x over previous
#include <cuda_runtime.h>
#include <cuda_bf16.h>
#include <math.h>
#include <cstdint>

// Problem constants
#define Bsz 2
#define Tq  2048
#define Dm  1024
#define Hh  16
#define DH  64

// ---------------------------------------------------------------------------
// Scratch (allocation-free rule: __device__ globals)
// ---------------------------------------------------------------------------
__device__ float g_q [Bsz * Tq * Dm];
__device__ float g_k [Bsz * Tq * Dm];
__device__ float g_v [Bsz * Tq * Dm];
__device__ float g_ao[Bsz * Tq * Dm];

// ---------------------------------------------------------------------------
// Helpers
// ---------------------------------------------------------------------------
__device__ __forceinline__ uint32_t smem_to_u32(const void* p) {
    uint32_t a;
    asm("{ .reg .u64 t; cvta.to.shared.u64 t, %1; cvt.u32.u64 %0, t; }"
        : "=r"(a) : "l"(p));
    return a;
}
__device__ __forceinline__ uint32_t f2tf32(float f) {
    uint32_t r;
    asm("cvt.rna.tf32.f32 %0, %1;" : "=r"(r) : "f"(f));
    return r;
}
__device__ __forceinline__ void mma_tf32(float* c,
                                         uint32_t a0, uint32_t a1, uint32_t a2, uint32_t a3,
                                         uint32_t b0, uint32_t b1)
{
    asm volatile(
        "mma.sync.aligned.m16n8k8.row.col.f32.tf32.tf32.f32 "
        "{%0,%1,%2,%3}, {%4,%5,%6,%7}, {%8,%9}, {%0,%1,%2,%3};"
        : "+f"(c[0]), "+f"(c[1]), "+f"(c[2]), "+f"(c[3])
        : "r"(a0), "r"(a1), "r"(a2), "r"(a3), "r"(b0), "r"(b1));
}

// ---------------------------------------------------------------------------
// GEMM via mma.sync tf32 (unchanged from R4): C = A[4096,1024] @ W[1024,1024]
// ---------------------------------------------------------------------------
#define GM_BM 128
#define GM_BN 128
#define GM_BK 32

#define SA_BYTES (128 * 36 * 4)
#define SB_BYTES (16 * 4 * 32 * 8)
#define SA0 0
#define SB0 SA_BYTES
#define SA1 (SB0 + SB_BYTES)
#define SB1 (SA1 + SA_BYTES)
#define SMEM_GEMM (SB1 + SB_BYTES)       // 69632

__global__ __launch_bounds__(256)
void gemm_mma(const float* __restrict__ A, const float* __restrict__ W,
              float* __restrict__ C)
{
    extern __shared__ char smem[];
    const uint32_t sb  = smem_to_u32(smem);
    const int tid  = threadIdx.x;
    const int lane = tid & 31;
    const int wid  = tid >> 5;
    const int wm   = wid & 3;
    const int wn   = wid >> 2;
    const int bm   = blockIdx.y * GM_BM;
    const int bn   = blockIdx.x * GM_BN;

    float acc[2][8][4];
#pragma unroll
    for (int i = 0; i < 2; i++)
#pragma unroll
        for (int j = 0; j < 8; j++)
#pragma unroll
            for (int q = 0; q < 4; q++) acc[i][j][q] = 0.f;

    float4 stA[4], stB[4];

    auto LDG = [&](int k0) {
#pragma unroll
        for (int it = 0; it < 4; it++) {
            int i = tid + it * 256;
            stA[it] = *(const float4*)(A + (size_t)(bm + (i >> 3)) * Dm + k0 + (i & 7) * 4);
        }
#pragma unroll
        for (int it = 0; it < 4; it++) {
            int i = tid + it * 256;
            stB[it] = *(const float4*)(W + (size_t)(k0 + (i >> 5)) * Dm + bn + (i & 31) * 4);
        }
    };

    auto STS = [&](uint32_t sa, uint32_t sbb) {
#pragma unroll
        for (int it = 0; it < 4; it++) {
            int i = tid + it * 256;
            int r = i >> 3, c4 = i & 7;
            uint32_t ad = sa + (uint32_t)(r * 144 + c4 * 16);
            asm volatile("st.shared.v4.b32 [%0], {%1,%2,%3,%4};" :: "r"(ad),
                "r"(f2tf32(stA[it].x)), "r"(f2tf32(stA[it].y)),
                "r"(f2tf32(stA[it].z)), "r"(f2tf32(stA[it].w)) : "memory");
        }
#pragma unroll
        for (int it = 0; it < 4; it++) {
            int i = tid + it * 256;
            int k = i >> 5, n4 = i & 31;
            int ktile = k >> 3, kk = k & 7;
            int slot = kk >> 2, kb = kk & 3;
            int ntile = n4 >> 1, nnb = (n4 & 1) << 2;
            uint32_t tb = sbb + (uint32_t)((ntile * 4 + ktile) * 256 + slot * 4);
            uint32_t l0 = (uint32_t)((((nnb + 0) << 2) | kb) ^ ntile);
            uint32_t l1 = (uint32_t)((((nnb + 1) << 2) | kb) ^ ntile);
            uint32_t l2 = (uint32_t)((((nnb + 2) << 2) | kb) ^ ntile);
            uint32_t l3 = (uint32_t)((((nnb + 3) << 2) | kb) ^ ntile);
            asm volatile("st.shared.b32 [%0], %1;" :: "r"(tb + l0 * 8), "r"(f2tf32(stB[it].x)) : "memory");
            asm volatile("st.shared.b32 [%0], %1;" :: "r"(tb + l1 * 8), "r"(f2tf32(stB[it].y)) : "memory");
            asm volatile("st.shared.b32 [%0], %1;" :: "r"(tb + l2 * 8), "r"(f2tf32(stB[it].z)) : "memory");
            asm volatile("st.shared.b32 [%0], %1;" :: "r"(tb + l3 * 8), "r"(f2tf32(stB[it].w)) : "memory");
        }
    };

    auto COMPUTE = [&](uint32_t sa, uint32_t sbb) {
#pragma unroll
        for (int ks = 0; ks < 4; ks++) {
            uint32_t af[2][4];
#pragma unroll
            for (int i = 0; i < 2; i++) {
                int row = wm * 32 + i * 16 + (lane >> 2);
                int col = ks * 8 + (lane & 3);
                uint32_t base = sa + (uint32_t)(row * 144 + col * 4);
                asm volatile("ld.shared.b32 %0, [%1];" : "=r"(af[i][0]) : "r"(base));
                asm volatile("ld.shared.b32 %0, [%1];" : "=r"(af[i][1]) : "r"(base + 8 * 144));
                asm volatile("ld.shared.b32 %0, [%1];" : "=r"(af[i][2]) : "r"(base + 16));
                asm volatile("ld.shared.b32 %0, [%1];" : "=r"(af[i][3]) : "r"(base + 8 * 144 + 16));
            }
            uint32_t bf[8][2];
#pragma unroll
            for (int j = 0; j < 8; j++) {
                int nt = wn * 8 + j;
                uint32_t ad = sbb + (uint32_t)((nt * 4 + ks) * 256 + ((lane ^ nt) & 31) * 8);
                asm volatile("ld.shared.v2.b32 {%0,%1}, [%2];"
                             : "=r"(bf[j][0]), "=r"(bf[j][1]) : "r"(ad));
            }
#pragma unroll
            for (int i = 0; i < 2; i++)
#pragma unroll
                for (int j = 0; j < 8; j++)
                    mma_tf32(acc[i][j], af[i][0], af[i][1], af[i][2], af[i][3],
                             bf[j][0], bf[j][1]);
        }
    };

    LDG(0);
    STS(sb + SA0, sb + SB0);
    __syncthreads();

#pragma unroll 1
    for (int ch = 0; ch < Dm / GM_BK; ch++) {
        const int p = ch & 1;
        if (ch + 1 < Dm / GM_BK) LDG((ch + 1) * GM_BK);
        COMPUTE(sb + (p ? SA1 : SA0), sb + (p ? SB1 : SB0));
        if (ch + 1 < Dm / GM_BK) STS(sb + (p ? SA0 : SA1), sb + (p ? SB0 : SB1));
        __syncthreads();
    }

#pragma unroll
    for (int i = 0; i < 2; i++) {
        int r0 = bm + wm * 32 + i * 16 + (lane >> 2);
#pragma unroll
        for (int j = 0; j < 8; j++) {
            int c = bn + wn * 64 + j * 8 + (lane & 3) * 2;
            *(float2*)(C + (size_t)r0 * Dm + c)       = make_float2(acc[i][j][0], acc[i][j][1]);
            *(float2*)(C + (size_t)(r0 + 8) * Dm + c) = make_float2(acc[i][j][2], acc[i][j][3]);
        }
    }
}

// ---------------------------------------------------------------------------
// Causal flash attention via mma.sync tf32.
// Grid (Tq/128, B*H), block 256 (8 warps). Warp w owns rows [w*16, w*16+16).
// QK^T: 3-term compensated tf32 (q_hi k_hi + q_lo k_hi + q_hi k_lo).
// PV:   single tf32.
// Q fragments (hi/lo) live in registers across the whole KV loop.
// smem (floats): P/Qstage [128][68] | Khi [64][68] | Klo [64][68] | V [64][72]
// ---------------------------------------------------------------------------
#define AT_P    0
#define AT_KHI  (128 * 68)                 // 8704
#define AT_KLO  (AT_KHI + 64 * 68)         // 13056
#define AT_V    (AT_KLO + 64 * 68)         // 17408
#define SMEM_ATTN ((AT_V + 64 * 72) * 4)   // 88064 bytes

__global__ __launch_bounds__(256, 1)
void attn_mma(const float* __restrict__ Q, const float* __restrict__ K,
              const float* __restrict__ V, float* __restrict__ O)
{
    extern __shared__ float sm[];
    const int tid  = threadIdx.x;
    const int lane = tid & 31;
    const int wid  = tid >> 5;
    const int qt   = blockIdx.x;
    const int bh   = blockIdx.y;
    const int b    = bh >> 4;
    const int h    = bh & 15;
    const int q0   = qt * 128;
    const size_t headoff = (size_t)b * Tq * Dm + (size_t)h * DH;

    const int lrow = lane >> 2;       // 0..7
    const int lcol = lane & 3;        // 0..3
    const float scale = 0.125f * 1.44269504089f;  // 1/sqrt(64) * log2(e)

    // ---- Stage Q tile (scaled) into sm[AT_P], then load frags to regs ----
    {
        const float* Qb = Q + headoff + (size_t)q0 * Dm;
#pragma unroll
        for (int t = 0; t < 8; t++) {
            int i = tid + t * 256;            // 2048 float4
            int r = i >> 4, c4 = i & 15;
            float4 v = *(const float4*)(Qb + (size_t)r * Dm + c4 * 4);
            v.x *= scale; v.y *= scale; v.z *= scale; v.w *= scale;
            *(float4*)&sm[AT_P + r * 68 + c4 * 4] = v;
        }
    }
    __syncthreads();

    uint32_t qhi[8][4], qlo[8][4];
    {
        const int row = wid * 16 + lrow;
#pragma unroll
        for (int ks = 0; ks < 8; ks++) {
            int col = ks * 8 + lcol;
            float f0 = sm[AT_P + row * 68 + col];
            float f1 = sm[AT_P + (row + 8) * 68 + col];
            float f2 = sm[AT_P + row * 68 + col + 4];
            float f3 = sm[AT_P + (row + 8) * 68 + col + 4];
            qhi[ks][0] = f2tf32(f0); qlo[ks][0] = f2tf32(f0 - __uint_as_float(qhi[ks][0]));
            qhi[ks][1] = f2tf32(f1); qlo[ks][1] = f2tf32(f1 - __uint_as_float(qhi[ks][1]));
            qhi[ks][2] = f2tf32(f2); qlo[ks][2] = f2tf32(f2 - __uint_as_float(qhi[ks][2]));
            qhi[ks][3] = f2tf32(f3); qlo[ks][3] = f2tf32(f3 - __uint_as_float(qhi[ks][3]));
        }
    }
    __syncthreads();   // Q staging region now free for P

    // ---- Online softmax state ----
    float m_i[2] = {-INFINITY, -INFINITY};
    float l_i[2] = {0.f, 0.f};
    float oacc[8][4];
#pragma unroll
    for (int j = 0; j < 8; j++)
#pragma unroll
        for (int q = 0; q < 4; q++) oacc[j][q] = 0.f;

    const int kmax = 2 * qt + 1;
    float4 rK[4], rV[4];

    // Prefetch kt=0
    {
        const float* Kb = K + headoff;
        const float* Vb = V + headoff;
#pragma unroll
        for (int t = 0; t < 4; t++) {
            int i = tid + t * 256;
            int r = i >> 4, c4 = i & 15;
            rK[t] = *(const float4*)(Kb + (size_t)r * Dm + c4 * 4);
            rV[t] = *(const float4*)(Vb + (size_t)r * Dm + c4 * 4);
        }
    }
    // Store kt=0 tiles
    auto STS_KV = [&]() {
#pragma unroll
        for (int t = 0; t < 4; t++) {
            int i = tid + t * 256;
            int r = i >> 4, c4 = i & 15;
            float4 kv = rK[t];
            uint32_t hx = f2tf32(kv.x), hy = f2tf32(kv.y), hz = f2tf32(kv.z), hw = f2tf32(kv.w);
            uint32_t lx = f2tf32(kv.x - __uint_as_float(hx));
            uint32_t ly = f2tf32(kv.y - __uint_as_float(hy));
            uint32_t lz = f2tf32(kv.z - __uint_as_float(hz));
            uint32_t lw = f2tf32(kv.w - __uint_as_float(hw));
            *(float4*)&sm[AT_KHI + r * 68 + c4 * 4] =
                make_float4(__uint_as_float(hx), __uint_as_float(hy),
                            __uint_as_float(hz), __uint_as_float(hw));
            *(float4*)&sm[AT_KLO + r * 68 + c4 * 4] =
                make_float4(__uint_as_float(lx), __uint_as_float(ly),
                            __uint_as_float(lz), __uint_as_float(lw));
            float4 vv = rV[t];
            *(float4*)&sm[AT_V + r * 72 + c4 * 4] =
                make_float4(__uint_as_float(f2tf32(vv.x)), __uint_as_float(f2tf32(vv.y)),
                            __uint_as_float(f2tf32(vv.z)), __uint_as_float(f2tf32(vv.w)));
        }
    };
    STS_KV();
    __syncthreads();

#pragma unroll 1
    for (int kt = 0; kt <= kmax; kt++) {
        // Prefetch next K/V into regs
        if (kt < kmax) {
            const float* Kb = K + headoff + (size_t)((kt + 1) * 64) * Dm;
            const float* Vb = V + headoff + (size_t)((kt + 1) * 64) * Dm;
#pragma unroll
            for (int t = 0; t < 4; t++) {
                int i = tid + t * 256;
                int r = i >> 4, c4 = i & 15;
                rK[t] = *(const float4*)(Kb + (size_t)r * Dm + c4 * 4);
                rV[t] = *(const float4*)(Vb + (size_t)r * Dm + c4 * 4);
            }
        }

        // ---- S = Q K^T (compensated tf32) ----
        float sacc[8][4];
#pragma unroll
        for (int j = 0; j < 8; j++)
#pragma unroll
            for (int q = 0; q < 4; q++) sacc[j][q] = 0.f;

#pragma unroll
        for (int ks = 0; ks < 8; ks++) {
            int dcol = ks * 8 + lcol;
#pragma unroll
            for (int j = 0; j < 8; j++) {
                int key = j * 8 + lrow;
                uint32_t bh0 = __float_as_uint(sm[AT_KHI + key * 68 + dcol]);
                uint32_t bh1 = __float_as_uint(sm[AT_KHI + key * 68 + dcol + 4]);
                uint32_t bl0 = __float_as_uint(sm[AT_KLO + key * 68 + dcol]);
                uint32_t bl1 = __float_as_uint(sm[AT_KLO + key * 68 + dcol + 4]);
                mma_tf32(sacc[j], qhi[ks][0], qhi[ks][1], qhi[ks][2], qhi[ks][3], bh0, bh1);
                mma_tf32(sacc[j], qlo[ks][0], qlo[ks][1], qlo[ks][2], qlo[ks][3], bh0, bh1);
                mma_tf32(sacc[j], qhi[ks][0], qhi[ks][1], qhi[ks][2], qhi[ks][3], bl0, bl1);
            }
        }

        // ---- Causal mask (only on the two diagonal-straddling tiles) ----
        if (kt >= 2 * qt) {
            int rowg0 = q0 + wid * 16 + lrow;
            int colg0 = kt * 64 + lcol * 2;
#pragma unroll
            for (int j = 0; j < 8; j++) {
                int c0 = colg0 + j * 8;
                if (c0     > rowg0)     sacc[j][0] = -INFINITY;
                if (c0 + 1 > rowg0)     sacc[j][1] = -INFINITY;
                if (c0     > rowg0 + 8) sacc[j][2] = -INFINITY;
                if (c0 + 1 > rowg0 + 8) sacc[j][3] = -INFINITY;
            }
        }

        // ---- Online softmax (base-2), store P (tf32) to smem ----
#pragma unroll
        for (int h2 = 0; h2 < 2; h2++) {
            const int co = h2 * 2;
            float rmax = -INFINITY;
#pragma unroll
            for (int j = 0; j < 8; j++)
                rmax = fmaxf(rmax, fmaxf(sacc[j][co], sacc[j][co + 1]));
            rmax = fmaxf(rmax, __shfl_xor_sync(0xffffffffu, rmax, 1));
            rmax = fmaxf(rmax, __shfl_xor_sync(0xffffffffu, rmax, 2));

            float mnew = fmaxf(m_i[h2], rmax);
            float sc = exp2f(m_i[h2] - mnew);
            m_i[h2] = mnew;

            float rsum = 0.f;
            const int prow = wid * 16 + lrow + h2 * 8;
#pragma unroll
            for (int j = 0; j < 8; j++) {
                float p0 = exp2f(sacc[j][co]     - mnew);
                float p1 = exp2f(sacc[j][co + 1] - mnew);
                rsum += p0 + p1;
                int pc = j * 8 + lcol * 2;
                *(float2*)&sm[AT_P + prow * 68 + pc] =
                    make_float2(__uint_as_float(f2tf32(p0)), __uint_as_float(f2tf32(p1)));
                oacc[j][co]     *= sc;
                oacc[j][co + 1] *= sc;
            }
            rsum += __shfl_xor_sync(0xffffffffu, rsum, 1);
            rsum += __shfl_xor_sync(0xffffffffu, rsum, 2);
            l_i[h2] = l_i[h2] * sc + rsum;
        }
        __syncwarp();

        // ---- O += P @ V ----
        {
            const int prow = wid * 16 + lrow;
#pragma unroll
            for (int ks = 0; ks < 8; ks++) {
                int pcol = ks * 8 + lcol;
                uint32_t a0 = __float_as_uint(sm[AT_P + prow * 68 + pcol]);
                uint32_t a1 = __float_as_uint(sm[AT_P + (prow + 8) * 68 + pcol]);
                uint32_t a2 = __float_as_uint(sm[AT_P + prow * 68 + pcol + 4]);
                uint32_t a3 = __float_as_uint(sm[AT_P + (prow + 8) * 68 + pcol + 4]);
#pragma unroll
                for (int j = 0; j < 8; j++) {
                    int dh = j * 8 + lrow;
                    uint32_t b0 = __float_as_uint(sm[AT_V + (ks * 8 + lcol) * 72 + dh]);
                    uint32_t b1 = __float_as_uint(sm[AT_V + (ks * 8 + 4 + lcol) * 72 + dh]);
                    mma_tf32(oacc[j], a0, a1, a2, a3, b0, b1);
                }
            }
        }
        __syncthreads();

        if (kt < kmax) {
            STS_KV();
            __syncthreads();
        }
    }

    // ---- Epilogue: normalize, write out ----
#pragma unroll
    for (int h2 = 0; h2 < 2; h2++) {
        float inv = 1.0f / l_i[h2];
        int rowg = q0 + wid * 16 + lrow + h2 * 8;
        float* Ob = O + headoff + (size_t)rowg * Dm;
        const int co = h2 * 2;
#pragma unroll
        for (int j = 0; j < 8; j++) {
            int c = j * 8 + lcol * 2;
            *(float2*)(Ob + c) = make_float2(oacc[j][co] * inv, oacc[j][co + 1] * inv);
        }
    }
}

// ---------------------------------------------------------------------------
// Launch.  Inputs: 0=x, 1=mask(unused), 2=Wq, 3=Wk, 4=Wv, 5=Wo
// ---------------------------------------------------------------------------
extern "C" void kernel_launch(void* const* d_in, const int* in_sizes, int n_in,
                              void* d_out, int out_size)
{
    const float* x  = (const float*)d_in[0];
    const float* Wq = (const float*)d_in[2];
    const float* Wk = (const float*)d_in[3];
    const float* Wv = (const float*)d_in[4];
    const float* Wo = (const float*)d_in[5];
    float* out = (float*)d_out;

    void *pq, *pk, *pv, *pao;
    cudaGetSymbolAddress(&pq,  g_q);
    cudaGetSymbolAddress(&pk,  g_k);
    cudaGetSymbolAddress(&pv,  g_v);
    cudaGetSymbolAddress(&pao, g_ao);

    cudaFuncSetAttribute(gemm_mma, cudaFuncAttributeMaxDynamicSharedMemorySize, SMEM_GEMM);
    cudaFuncSetAttribute(attn_mma, cudaFuncAttributeMaxDynamicSharedMemorySize, SMEM_ATTN);

    const int M = Bsz * Tq;                 // 4096
    dim3 gG(Dm / GM_BN, M / GM_BM);         // (8, 32)
    dim3 gAttn(Tq / 128, Bsz * Hh);         // (16, 32)

    gemm_mma<<<gG, 256, SMEM_GEMM>>>(x, Wq, (float*)pq);
    gemm_mma<<<gG, 256, SMEM_GEMM>>>(x, Wk, (float*)pk);
    gemm_mma<<<gG, 256, SMEM_GEMM>>>(x, Wv, (float*)pv);

    attn_mma<<<gAttn, 256, SMEM_ATTN>>>((const float*)pq, (const float*)pk,
                                        (const float*)pv, (float*)pao);

    gemm_mma<<<gG, 256, SMEM_GEMM>>>((const float*)pao, Wo, out);
}

// round 9
// speedup vs baseline: 5.2720x; 1.5557x over previous
#include <cuda_runtime.h>
#include <cuda_fp16.h>
#include <math.h>
#include <cstdint>

// Problem constants
#define Bsz 2
#define Tq  2048
#define Dm  1024
#define Hh  16
#define DH  64

// ---------------------------------------------------------------------------
// Scratch (allocation-free rule: __device__ globals)
// ---------------------------------------------------------------------------
__device__ float g_q [Bsz * Tq * Dm];
__device__ float g_k [Bsz * Tq * Dm];
__device__ float g_v [Bsz * Tq * Dm];
__device__ float g_ao[Bsz * Tq * Dm];

// ---------------------------------------------------------------------------
// Helpers
// ---------------------------------------------------------------------------
__device__ __forceinline__ uint32_t smem_to_u32(const void* p) {
    uint32_t a;
    asm("{ .reg .u64 t; cvta.to.shared.u64 t, %1; cvt.u32.u64 %0, t; }"
        : "=r"(a) : "l"(p));
    return a;
}
__device__ __forceinline__ uint32_t pack_h2(float x, float y) {
    __half2 h = __floats2half2_rn(x, y);
    return *reinterpret_cast<uint32_t*>(&h);
}
__device__ __forceinline__ void split_h2(float x, float y, uint32_t& hi, uint32_t& lo) {
    __half hx = __float2half_rn(x), hy = __float2half_rn(y);
    __half lx = __float2half_rn(x - __half2float(hx));
    __half ly = __float2half_rn(y - __half2float(hy));
    __half2 H = __halves2half2(hx, hy), L = __halves2half2(lx, ly);
    hi = *reinterpret_cast<uint32_t*>(&H);
    lo = *reinterpret_cast<uint32_t*>(&L);
}
__device__ __forceinline__ void mma_f16(float* c, const uint32_t* a,
                                        uint32_t b0, uint32_t b1)
{
    asm volatile(
        "mma.sync.aligned.m16n8k16.row.col.f32.f16.f16.f32 "
        "{%0,%1,%2,%3}, {%4,%5,%6,%7}, {%8,%9}, {%0,%1,%2,%3};"
        : "+f"(c[0]), "+f"(c[1]), "+f"(c[2]), "+f"(c[3])
        : "r"(a[0]), "r"(a[1]), "r"(a[2]), "r"(a[3]), "r"(b0), "r"(b1));
}

// ---------------------------------------------------------------------------
// fp16 GEMM via mma.sync m16n8k16: C[4096,1024] = A[4096,1024] @ W[1024,1024]
// CTA 128x128, BK=32, 8 warps (warp 32x64), double-buffered. (unchanged R6)
// A smem: [128 rows][40 halves] (80B stride, 32 data halves/row)
// B smem: fragment-order [ntile(16)][kstep(2)][lane(32)][reg(2)] u32
// ---------------------------------------------------------------------------
#define GM_BK 32
#define GA_BYTES (128 * 80)
#define GB_BYTES (16 * 2 * 32 * 8)
#define GSA0 0
#define GSB0 GA_BYTES
#define GSA1 (GSB0 + GB_BYTES)
#define GSB1 (GSA1 + GA_BYTES)
#define SMEM_GEMM (GSB1 + GB_BYTES)      // 36864

__global__ __launch_bounds__(256)
void gemm_mma(const float* __restrict__ A, const float* __restrict__ W,
              float* __restrict__ C)
{
    extern __shared__ char smem[];
    const uint32_t sb  = smem_to_u32(smem);
    const int tid  = threadIdx.x;
    const int lane = tid & 31;
    const int lrow = lane >> 2;
    const int lcol = lane & 3;
    const int wid  = tid >> 5;
    const int wm   = wid & 3;
    const int wn   = wid >> 2;
    const int bm   = blockIdx.y * 128;
    const int bn   = blockIdx.x * 128;

    float acc[2][8][4];
#pragma unroll
    for (int i = 0; i < 2; i++)
#pragma unroll
        for (int j = 0; j < 8; j++)
#pragma unroll
            for (int q = 0; q < 4; q++) acc[i][j][q] = 0.f;

    float4 stA[4], stB[4];

    auto LDG = [&](int k0) {
#pragma unroll
        for (int it = 0; it < 4; it++) {
            int i = tid + it * 256;
            stA[it] = *(const float4*)(A + (size_t)(bm + (i >> 3)) * Dm + k0 + (i & 7) * 4);
        }
#pragma unroll
        for (int it = 0; it < 4; it++) {
            int i = tid + it * 256;
            stB[it] = *(const float4*)(W + (size_t)(k0 + (i >> 5)) * Dm + bn + (i & 31) * 4);
        }
    };

    auto STS = [&](uint32_t sa, uint32_t sbb) {
#pragma unroll
        for (int it = 0; it < 4; it++) {
            int i = tid + it * 256;
            int r = i >> 3, c4 = i & 7;
            uint32_t ad = sa + (uint32_t)(r * 80 + c4 * 8);
            uint32_t h01 = pack_h2(stA[it].x, stA[it].y);
            uint32_t h23 = pack_h2(stA[it].z, stA[it].w);
            asm volatile("st.shared.v2.b32 [%0], {%1,%2};"
                         :: "r"(ad), "r"(h01), "r"(h23) : "memory");
        }
#pragma unroll
        for (int it = 0; it < 4; it++) {
            int i = tid + it * 256;
            int k = i >> 5, n4 = i & 31;
            int kstep = k >> 4, kk = k & 15;
            int reg = kk >> 3, lc = (kk & 7) >> 1, hf = kk & 1;
            float vals[4] = {stB[it].x, stB[it].y, stB[it].z, stB[it].w};
#pragma unroll
            for (int e = 0; e < 4; e++) {
                int n = n4 * 4 + e;
                int ntile = n >> 3, nl = n & 7;
                int lanep = (nl * 4 + lc + ntile) & 31;
                uint32_t ad = sbb + (uint32_t)(((ntile * 2 + kstep) * 32 + lanep) * 8
                                               + reg * 4 + hf * 2);
                asm volatile("st.shared.b16 [%0], %1;"
                             :: "r"(ad), "h"(__half_as_ushort(__float2half_rn(vals[e])))
                             : "memory");
            }
        }
    };

    auto COMPUTE = [&](uint32_t sa, uint32_t sbb) {
#pragma unroll
        for (int ks = 0; ks < 2; ks++) {
            uint32_t af[2][4];
#pragma unroll
            for (int i = 0; i < 2; i++) {
                int row = wm * 32 + i * 16 + lrow;
                uint32_t base = sa + (uint32_t)(row * 80 + ks * 32 + lcol * 4);
                asm volatile("ld.shared.b32 %0, [%1];" : "=r"(af[i][0]) : "r"(base));
                asm volatile("ld.shared.b32 %0, [%1];" : "=r"(af[i][1]) : "r"(base + 640));
                asm volatile("ld.shared.b32 %0, [%1];" : "=r"(af[i][2]) : "r"(base + 16));
                asm volatile("ld.shared.b32 %0, [%1];" : "=r"(af[i][3]) : "r"(base + 656));
            }
            uint32_t bf[8][2];
#pragma unroll
            for (int j = 0; j < 8; j++) {
                int nt = wn * 8 + j;
                uint32_t ad = sbb + (uint32_t)(((nt * 2 + ks) * 32 + ((lane + nt) & 31)) * 8);
                asm volatile("ld.shared.v2.b32 {%0,%1}, [%2];"
                             : "=r"(bf[j][0]), "=r"(bf[j][1]) : "r"(ad));
            }
#pragma unroll
            for (int i = 0; i < 2; i++)
#pragma unroll
                for (int j = 0; j < 8; j++)
                    mma_f16(acc[i][j], af[i], bf[j][0], bf[j][1]);
        }
    };

    LDG(0);
    STS(sb + GSA0, sb + GSB0);
    __syncthreads();

#pragma unroll 1
    for (int ch = 0; ch < Dm / GM_BK; ch++) {
        const int p = ch & 1;
        if (ch + 1 < Dm / GM_BK) LDG((ch + 1) * GM_BK);
        COMPUTE(sb + (p ? GSA1 : GSA0), sb + (p ? GSB1 : GSB0));
        if (ch + 1 < Dm / GM_BK) STS(sb + (p ? GSA0 : GSA1), sb + (p ? GSB0 : GSB1));
        __syncthreads();
    }

#pragma unroll
    for (int i = 0; i < 2; i++) {
        int r0 = bm + wm * 32 + i * 16 + lrow;
#pragma unroll
        for (int j = 0; j < 8; j++) {
            int c = bn + wn * 64 + j * 8 + lcol * 2;
            *(float2*)(C + (size_t)r0 * Dm + c)       = make_float2(acc[i][j][0], acc[i][j][1]);
            *(float2*)(C + (size_t)(r0 + 8) * Dm + c) = make_float2(acc[i][j][2], acc[i][j][3]);
        }
    }
}

// ---------------------------------------------------------------------------
// Causal flash attention via mma.sync fp16 (m16n8k16).
// FIXED from R6: attention K and P rows are 64 halves (128 B) wide; row
// stride is now 144 B (GEMM's 80 B stride caused row overlap -> garbage).
// 144 B stride => addr/4 = 36*row + ..., 36 mod 32 = 4 => conflict-free frags.
// smem bytes:
//   AT_P    0      Q stage fp32 [128][68] = 34816; reused as P [128 rows][144B]
//   AT_KHI  34816  K hi [64 rows][144B] = 9216
//   AT_KLO  44032  K lo [64 rows][144B] = 9216
//   AT_VF   53248  V frag-order [nt(8)][ks(4)][lane(32)][reg(2)] u32 = 8192
// ---------------------------------------------------------------------------
#define AT_P    0
#define AT_KHI  34816
#define AT_KLO  44032
#define AT_VF   53248
#define SMEM_ATTN 61440
#define KP_STRIDE 144

__global__ __launch_bounds__(256, 1)
void attn_mma(const float* __restrict__ Q, const float* __restrict__ K,
              const float* __restrict__ V, float* __restrict__ O)
{
    extern __shared__ char smem[];
    float* smf = (float*)smem;
    const uint32_t sb = smem_to_u32(smem);
    const int tid  = threadIdx.x;
    const int lane = tid & 31;
    const int lrow = lane >> 2;
    const int lcol = lane & 3;
    const int wid  = tid >> 5;
    const int qt   = blockIdx.x;
    const int bh   = blockIdx.y;
    const int b    = bh >> 4;
    const int h    = bh & 15;
    const int q0   = qt * 128;
    const size_t headoff = (size_t)b * Tq * Dm + (size_t)h * DH;

    const float scale = 0.125f * 1.44269504089f;  // 1/sqrt(64) * log2(e)

    // ---- Stage Q (scaled, fp32) then build hi/lo fp16 fragments ----
    {
        const float* Qb = Q + headoff + (size_t)q0 * Dm;
#pragma unroll
        for (int t = 0; t < 8; t++) {
            int i = tid + t * 256;
            int r = i >> 4, c4 = i & 15;
            float4 v = *(const float4*)(Qb + (size_t)r * Dm + c4 * 4);
            v.x *= scale; v.y *= scale; v.z *= scale; v.w *= scale;
            *(float4*)&smf[r * 68 + c4 * 4] = v;
        }
    }
    __syncthreads();

    uint32_t qhi[4][4], qlo[4][4];
    {
        const int row = wid * 16 + lrow;
#pragma unroll
        for (int ks = 0; ks < 4; ks++) {
            int c = ks * 16 + lcol * 2;
            float2 f0 = *(float2*)&smf[row * 68 + c];
            float2 f1 = *(float2*)&smf[(row + 8) * 68 + c];
            float2 f2 = *(float2*)&smf[row * 68 + c + 8];
            float2 f3 = *(float2*)&smf[(row + 8) * 68 + c + 8];
            split_h2(f0.x, f0.y, qhi[ks][0], qlo[ks][0]);
            split_h2(f1.x, f1.y, qhi[ks][1], qlo[ks][1]);
            split_h2(f2.x, f2.y, qhi[ks][2], qlo[ks][2]);
            split_h2(f3.x, f3.y, qhi[ks][3], qlo[ks][3]);
        }
    }
    __syncthreads();   // Q staging region now free for P

    float m_i[2] = {-INFINITY, -INFINITY};
    float l_i[2] = {0.f, 0.f};
    float oacc[8][4];
#pragma unroll
    for (int j = 0; j < 8; j++)
#pragma unroll
        for (int q = 0; q < 4; q++) oacc[j][q] = 0.f;

    const int kmax = 2 * qt + 1;
    float4 rK[4], rV[4];

    auto LDG_KV = [&](int kt) {
        const float* Kb = K + headoff + (size_t)(kt * 64) * Dm;
        const float* Vb = V + headoff + (size_t)(kt * 64) * Dm;
#pragma unroll
        for (int t = 0; t < 4; t++) {
            int i = tid + t * 256;
            int r = i >> 4, c4 = i & 15;
            rK[t] = *(const float4*)(Kb + (size_t)r * Dm + c4 * 4);
            rV[t] = *(const float4*)(Vb + (size_t)r * Dm + c4 * 4);
        }
    };

    auto STS_KV = [&]() {
#pragma unroll
        for (int t = 0; t < 4; t++) {
            int i = tid + t * 256;
            int key = i >> 4, c4 = i & 15;     // c4*4 halves within 64-wide row
            float4 kv = rK[t];
            uint32_t h01, l01, h23, l23;
            split_h2(kv.x, kv.y, h01, l01);
            split_h2(kv.z, kv.w, h23, l23);
            uint32_t rad = (uint32_t)(key * KP_STRIDE + c4 * 8);
            asm volatile("st.shared.v2.b32 [%0], {%1,%2};"
                         :: "r"(sb + AT_KHI + rad), "r"(h01), "r"(h23) : "memory");
            asm volatile("st.shared.v2.b32 [%0], {%1,%2};"
                         :: "r"(sb + AT_KLO + rad), "r"(l01), "r"(l23) : "memory");
            // V fragment-order scatter (k-dim = key, n-dim = dh)
            int kstep = key >> 4, kk = key & 15;
            int reg = kk >> 3, lc = (kk & 7) >> 1, hf = kk & 1;
            float vv[4] = {rV[t].x, rV[t].y, rV[t].z, rV[t].w};
#pragma unroll
            for (int e = 0; e < 4; e++) {
                int dh = c4 * 4 + e;
                int ntile = dh >> 3, nl = dh & 7;
                int lanep = (nl * 4 + lc + ntile) & 31;
                uint32_t ad = sb + AT_VF + (uint32_t)(((ntile * 4 + kstep) * 32 + lanep) * 8
                                                      + reg * 4 + hf * 2);
                asm volatile("st.shared.b16 [%0], %1;"
                             :: "r"(ad), "h"(__half_as_ushort(__float2half_rn(vv[e])))
                             : "memory");
            }
        }
    };

    LDG_KV(0);
    STS_KV();
    __syncthreads();

#pragma unroll 1
    for (int kt = 0; kt <= kmax; kt++) {
        if (kt < kmax) LDG_KV(kt + 1);

        // ---- S = Q K^T (compensated fp16) ----
        float sacc[8][4];
#pragma unroll
        for (int j = 0; j < 8; j++)
#pragma unroll
            for (int q = 0; q < 4; q++) sacc[j][q] = 0.f;

#pragma unroll
        for (int ks = 0; ks < 4; ks++) {
#pragma unroll
            for (int j = 0; j < 8; j++) {
                uint32_t kb = sb + AT_KHI
                    + (uint32_t)((j * 8 + lrow) * KP_STRIDE + ks * 32 + lcol * 4);
                uint32_t kh0, kh1, kl0, kl1;
                asm volatile("ld.shared.b32 %0, [%1];" : "=r"(kh0) : "r"(kb));
                asm volatile("ld.shared.b32 %0, [%1];" : "=r"(kh1) : "r"(kb + 16));
                asm volatile("ld.shared.b32 %0, [%1];" : "=r"(kl0) : "r"(kb + (AT_KLO - AT_KHI)));
                asm volatile("ld.shared.b32 %0, [%1];" : "=r"(kl1) : "r"(kb + (AT_KLO - AT_KHI) + 16));
                mma_f16(sacc[j], qhi[ks], kh0, kh1);
                mma_f16(sacc[j], qlo[ks], kh0, kh1);
                mma_f16(sacc[j], qhi[ks], kl0, kl1);
            }
        }

        // ---- Causal mask (diagonal-straddling tiles only) ----
        if (kt >= 2 * qt) {
            int rowg0 = q0 + wid * 16 + lrow;
            int colg0 = kt * 64 + lcol * 2;
#pragma unroll
            for (int j = 0; j < 8; j++) {
                int c0 = colg0 + j * 8;
                if (c0     > rowg0)     sacc[j][0] = -INFINITY;
                if (c0 + 1 > rowg0)     sacc[j][1] = -INFINITY;
                if (c0     > rowg0 + 8) sacc[j][2] = -INFINITY;
                if (c0 + 1 > rowg0 + 8) sacc[j][3] = -INFINITY;
            }
        }

        // ---- Online softmax (base-2); P -> smem as fp16 ----
#pragma unroll
        for (int h2 = 0; h2 < 2; h2++) {
            const int co = h2 * 2;
            float rmax = -INFINITY;
#pragma unroll
            for (int j = 0; j < 8; j++)
                rmax = fmaxf(rmax, fmaxf(sacc[j][co], sacc[j][co + 1]));
            rmax = fmaxf(rmax, __shfl_xor_sync(0xffffffffu, rmax, 1));
            rmax = fmaxf(rmax, __shfl_xor_sync(0xffffffffu, rmax, 2));

            float mnew = fmaxf(m_i[h2], rmax);
            float sc = exp2f(m_i[h2] - mnew);
            m_i[h2] = mnew;

            float rsum = 0.f;
            const int prow = wid * 16 + lrow + h2 * 8;
#pragma unroll
            for (int j = 0; j < 8; j++) {
                float p0 = exp2f(sacc[j][co]     - mnew);
                float p1 = exp2f(sacc[j][co + 1] - mnew);
                rsum += p0 + p1;
                uint32_t ad = sb + AT_P
                    + (uint32_t)(prow * KP_STRIDE + (j * 8 + lcol * 2) * 2);
                uint32_t pp = pack_h2(p0, p1);
                asm volatile("st.shared.b32 [%0], %1;" :: "r"(ad), "r"(pp) : "memory");
                oacc[j][co]     *= sc;
                oacc[j][co + 1] *= sc;
            }
            rsum += __shfl_xor_sync(0xffffffffu, rsum, 1);
            rsum += __shfl_xor_sync(0xffffffffu, rsum, 2);
            l_i[h2] = l_i[h2] * sc + rsum;
        }
        __syncwarp();

        // ---- O += P @ V (single fp16) ----
        {
            const int prow = wid * 16 + lrow;
#pragma unroll
            for (int ks = 0; ks < 4; ks++) {
                uint32_t pa[4];
                uint32_t pb = sb + AT_P + (uint32_t)(prow * KP_STRIDE + ks * 32 + lcol * 4);
                asm volatile("ld.shared.b32 %0, [%1];" : "=r"(pa[0]) : "r"(pb));
                asm volatile("ld.shared.b32 %0, [%1];" : "=r"(pa[1]) : "r"(pb + 8 * KP_STRIDE));
                asm volatile("ld.shared.b32 %0, [%1];" : "=r"(pa[2]) : "r"(pb + 16));
                asm volatile("ld.shared.b32 %0, [%1];" : "=r"(pa[3]) : "r"(pb + 8 * KP_STRIDE + 16));
#pragma unroll
                for (int j = 0; j < 8; j++) {
                    uint32_t v0, v1;
                    uint32_t ad = sb + AT_VF
                        + (uint32_t)(((j * 4 + ks) * 32 + ((lane + j) & 31)) * 8);
                    asm volatile("ld.shared.v2.b32 {%0,%1}, [%2];"
                                 : "=r"(v0), "=r"(v1) : "r"(ad));
                    mma_f16(oacc[j], pa, v0, v1);
                }
            }
        }
        __syncthreads();

        if (kt < kmax) {
            STS_KV();
            __syncthreads();
        }
    }

    // ---- Epilogue ----
#pragma unroll
    for (int h2 = 0; h2 < 2; h2++) {
        float inv = 1.0f / l_i[h2];
        int rowg = q0 + wid * 16 + lrow + h2 * 8;
        float* Ob = O + headoff + (size_t)rowg * Dm;
        const int co = h2 * 2;
#pragma unroll
        for (int j = 0; j < 8; j++) {
            int c = j * 8 + lcol * 2;
            *(float2*)(Ob + c) = make_float2(oacc[j][co] * inv, oacc[j][co + 1] * inv);
        }
    }
}

// ---------------------------------------------------------------------------
// Launch.  Inputs: 0=x, 1=mask(unused), 2=Wq, 3=Wk, 4=Wv, 5=Wo
// ---------------------------------------------------------------------------
extern "C" void kernel_launch(void* const* d_in, const int* in_sizes, int n_in,
                              void* d_out, int out_size)
{
    const float* x  = (const float*)d_in[0];
    const float* Wq = (const float*)d_in[2];
    const float* Wk = (const float*)d_in[3];
    const float* Wv = (const float*)d_in[4];
    const float* Wo = (const float*)d_in[5];
    float* out = (float*)d_out;

    void *pq, *pk, *pv, *pao;
    cudaGetSymbolAddress(&pq,  g_q);
    cudaGetSymbolAddress(&pk,  g_k);
    cudaGetSymbolAddress(&pv,  g_v);
    cudaGetSymbolAddress(&pao, g_ao);

    cudaFuncSetAttribute(gemm_mma, cudaFuncAttributeMaxDynamicSharedMemorySize, SMEM_GEMM);
    cudaFuncSetAttribute(attn_mma, cudaFuncAttributeMaxDynamicSharedMemorySize, SMEM_ATTN);

    const int M = Bsz * Tq;                 // 4096
    dim3 gG(Dm / 128, M / 128);             // (8, 32)
    dim3 gAttn(Tq / 128, Bsz * Hh);         // (16, 32)

    gemm_mma<<<gG, 256, SMEM_GEMM>>>(x, Wq, (float*)pq);
    gemm_mma<<<gG, 256, SMEM_GEMM>>>(x, Wk, (float*)pk);
    gemm_mma<<<gG, 256, SMEM_GEMM>>>(x, Wv, (float*)pv);

    attn_mma<<<gAttn, 256, SMEM_ATTN>>>((const float*)pq, (const float*)pk,
                                        (const float*)pv, (float*)pao);

    gemm_mma<<<gG, 256, SMEM_GEMM>>>((const float*)pao, Wo, out);
}